// round 1
// baseline (speedup 1.0000x reference)
#include <cuda_runtime.h>
#include <math_constants.h>

#define NUM_VIEW 300

// Precomputed view codebook: (x, y, z, |v|^2) per view.
__device__ float4 g_views[NUM_VIEW];

__global__ void np_init_views_kernel() {
    int i = threadIdx.x;
    if (i < NUM_VIEW) {
        // Match numpy float64 construction exactly, then cast to float32.
        double di  = (double)i;
        double zi  = (2.0 * di + 1.0) / (double)NUM_VIEW - 1.0;
        double r2  = 1.0 - zi * zi;
        if (r2 < 0.0) r2 = 0.0;
        double r   = sqrt(r2);
        const double PHI = (sqrt(5.0) - 1.0) * 0.5;
        double ang = 2.0 * di * CUDART_PI * PHI;
        float xf = (float)(r * cos(ang));
        float yf = (float)(r * sin(ang));
        float zf = (float)zi;
        // fp32 sum-of-squares, no FMA contraction (match jnp.sum(views*views))
        float vv = __fadd_rn(__fadd_rn(__fmul_rn(xf, xf), __fmul_rn(yf, yf)),
                             __fmul_rn(zf, zf));
        g_views[i] = make_float4(xf, yf, zf, vv);
    }
}

// MODE 0: indices written as float32 (output = 13*P floats)
// MODE 1: indices written as int64 bit-pattern (output = 14*P float slots)
template <int MODE>
__global__ void np_main_kernel(const float* __restrict__ normals,
                               const int*   __restrict__ idxs,
                               float*       __restrict__ out,
                               int N, int S, int P) {
    __shared__ float4 sv[NUM_VIEW];
    for (int i = threadIdx.x; i < NUM_VIEW; i += blockDim.x)
        sv[i] = g_views[i];
    __syncthreads();

    int p = blockIdx.x * blockDim.x + threadIdx.x;
    if (p >= P) return;

    int b   = p / S;
    int idx = idxs[p];
    const float* nptr = normals + ((long long)b * N + idx) * 3;
    float nx = __ldg(nptr + 0);
    float ny = __ldg(nptr + 1);
    float nz = __ldg(nptr + 2);

    // |n|^2 (fp32)
    float nn = nx * nx + ny * ny + nz * nz;

    // argmin over views of d2 = nn - 2*dot + |v|^2  (first-min wins, like argmin)
    float best = CUDART_INF_F;
    int   bi   = 0;
#pragma unroll 4
    for (int v = 0; v < NUM_VIEW; v++) {
        float4 V = sv[v];
        float dot = nx * V.x + ny * V.y + nz * V.z;
        float d   = nn - 2.0f * dot + V.w;
        if (d < best) { best = d; bi = v; }
    }

    // Rotation matrix from towards = -n, angle = 0 (R1 = I, so rot = R2).
    float ax_x = -nx, ax_y = -ny, ax_z = -nz;
    float ay_x = -ax_y;   // = ny
    float ay_y =  ax_x;   // = -nx
    float ay_z = 0.0f;
    if (ay_x * ay_x + ay_y * ay_y + ay_z * ay_z == 0.0f) {
        ay_x = 0.0f; ay_y = 1.0f; ay_z = 0.0f;
    }
    float inva = 1.0f / sqrtf(ax_x * ax_x + ax_y * ax_y + ax_z * ax_z);
    ax_x *= inva; ax_y *= inva; ax_z *= inva;
    float invy = 1.0f / sqrtf(ay_x * ay_x + ay_y * ay_y + ay_z * ay_z);
    ay_x *= invy; ay_y *= invy; ay_z *= invy;
    // az = cross(ax, ay)
    float az_x = ax_y * ay_z - ax_z * ay_y;
    float az_y = ax_z * ay_x - ax_x * ay_z;
    float az_z = ax_x * ay_y - ax_y * ay_x;

    // --- outputs ---
    float* out_xyz;
    float* out_rot;
    if (MODE == 0) {
        out[p] = (float)bi;
        out_xyz = out + P;
        out_rot = out + P + 3 * (long long)P;
    } else {
        ((long long*)out)[p] = (long long)bi;
        out_xyz = out + 2 * (long long)P;
        out_rot = out + 2 * (long long)P + 3 * (long long)P;
    }

    long long base3 = (long long)p * 3;
    out_xyz[base3 + 0] = nx;
    out_xyz[base3 + 1] = ny;
    out_xyz[base3 + 2] = nz;

    long long base9 = (long long)p * 9;
    // row-major [r][c]: col0 = ax, col1 = ay, col2 = az
    out_rot[base9 + 0] = ax_x;
    out_rot[base9 + 1] = ay_x;
    out_rot[base9 + 2] = az_x;
    out_rot[base9 + 3] = ax_y;
    out_rot[base9 + 4] = ay_y;
    out_rot[base9 + 5] = az_y;
    out_rot[base9 + 6] = ax_z;
    out_rot[base9 + 7] = ay_z;
    out_rot[base9 + 8] = az_z;
}

extern "C" void kernel_launch(void* const* d_in, const int* in_sizes, int n_in,
                              void* d_out, int out_size) {
    const float* normals = (const float*)d_in[0];
    const int*   idxs    = (const int*)d_in[1];
    float*       out     = (float*)d_out;

    const int B = 8;
    int P = in_sizes[1];            // B*S = 32768
    int S = P / B;                  // 4096
    int N = in_sizes[0] / (B * 3);  // 500000

    np_init_views_kernel<<<1, NUM_VIEW>>>();

    int threads = 256;
    int blocks  = (P + threads - 1) / threads;
    if (out_size == 14 * P) {
        np_main_kernel<1><<<blocks, threads>>>(normals, idxs, out, N, S, P);
    } else {
        np_main_kernel<0><<<blocks, threads>>>(normals, idxs, out, N, S, P);
    }
}

// round 2
// speedup vs baseline: 1.1193x; 1.1193x over previous
#include <cuda_runtime.h>
#include <math_constants.h>

#define NUM_VIEW 300

// Precomputed view codebook: (x, y, z, |v|^2) per view.
__device__ float4 g_views[NUM_VIEW];

__global__ void np_init_views_kernel() {
    int i = threadIdx.x;
    if (i < NUM_VIEW) {
        // Match numpy float64 construction exactly, then cast to float32.
        double di  = (double)i;
        double zi  = (2.0 * di + 1.0) / (double)NUM_VIEW - 1.0;
        double r2  = 1.0 - zi * zi;
        if (r2 < 0.0) r2 = 0.0;
        double r   = sqrt(r2);
        const double PHI = (sqrt(5.0) - 1.0) * 0.5;
        double ang = 2.0 * di * CUDART_PI * PHI;
        double s, c;
        sincos(ang, &s, &c);
        float xf = (float)(r * c);
        float yf = (float)(r * s);
        float zf = (float)zi;
        // fp32 sum-of-squares, no FMA contraction (match jnp.sum(views*views))
        float vv = __fadd_rn(__fadd_rn(__fmul_rn(xf, xf), __fmul_rn(yf, yf)),
                             __fmul_rn(zf, zf));
        g_views[i] = make_float4(xf, yf, zf, vv);
    }
}

__device__ __forceinline__ void np_merge(float& d0, int& i0, float d1, int i1) {
    // first-min (lowest index) wins on ties — exact jnp.argmin semantics
    if (d1 < d0 || (d1 == d0 && i1 < i0)) { d0 = d1; i0 = i1; }
}

// 2 threads per point. Lane h in {0,1} scans views [h*150, h*150+150).
// MODE 0: indices written as float32 (output = 13*P floats)
// MODE 1: indices written as int64 bit-pattern (output = 14*P float slots)
template <int MODE>
__global__ void np_main_kernel(const float* __restrict__ normals,
                               const int*   __restrict__ idxs,
                               float*       __restrict__ out,
                               int N, int S, int P) {
    __shared__ float4 sv[NUM_VIEW];
    for (int i = threadIdx.x; i < NUM_VIEW; i += blockDim.x)
        sv[i] = g_views[i];
    __syncthreads();

    int t = blockIdx.x * blockDim.x + threadIdx.x;
    int p = t >> 1;
    int h = t & 1;
    if (p >= P) return;

    int b   = p / S;
    int idx = idxs[p];
    const float* nptr = normals + ((long long)b * N + idx) * 3;
    float nx = __ldg(nptr + 0);
    float ny = __ldg(nptr + 1);
    float nz = __ldg(nptr + 2);

    float nn = nx * nx + ny * ny + nz * nz;

    // --- argmin over this thread's 150 views: 4 independent accumulators ---
    int base = h * 150;
    float bd0 = CUDART_INF_F, bd1 = CUDART_INF_F,
          bd2 = CUDART_INF_F, bd3 = CUDART_INF_F;
    int   bi0 = 0, bi1 = 0, bi2 = 0, bi3 = 0;

    int v = base;
#pragma unroll 1
    for (int k = 0; k < 37; k++) {
        float4 V0 = sv[v + 0];
        float4 V1 = sv[v + 1];
        float4 V2 = sv[v + 2];
        float4 V3 = sv[v + 3];
        float dot0 = nx * V0.x + ny * V0.y + nz * V0.z;
        float dot1 = nx * V1.x + ny * V1.y + nz * V1.z;
        float dot2 = nx * V2.x + ny * V2.y + nz * V2.z;
        float dot3 = nx * V3.x + ny * V3.y + nz * V3.z;
        float d0 = nn - 2.0f * dot0 + V0.w;
        float d1 = nn - 2.0f * dot1 + V1.w;
        float d2 = nn - 2.0f * dot2 + V2.w;
        float d3 = nn - 2.0f * dot3 + V3.w;
        if (d0 < bd0) { bd0 = d0; bi0 = v + 0; }
        if (d1 < bd1) { bd1 = d1; bi1 = v + 1; }
        if (d2 < bd2) { bd2 = d2; bi2 = v + 2; }
        if (d3 < bd3) { bd3 = d3; bi3 = v + 3; }
        v += 4;
    }
    // tail: 2 remaining views (148, 149 within the half)
    {
        float4 V0 = sv[v + 0];
        float4 V1 = sv[v + 1];
        float dot0 = nx * V0.x + ny * V0.y + nz * V0.z;
        float dot1 = nx * V1.x + ny * V1.y + nz * V1.z;
        float d0 = nn - 2.0f * dot0 + V0.w;
        float d1 = nn - 2.0f * dot1 + V1.w;
        if (d0 < bd0) { bd0 = d0; bi0 = v + 0; }
        if (d1 < bd1) { bd1 = d1; bi1 = v + 1; }
    }

    // merge 4 accumulators (index tie-break keeps exact first-min semantics)
    np_merge(bd0, bi0, bd1, bi1);
    np_merge(bd2, bi2, bd3, bi3);
    np_merge(bd0, bi0, bd2, bi2);

    // merge across the lane pair
    float od = __shfl_xor_sync(0xffffffffu, bd0, 1);
    int   oi = __shfl_xor_sync(0xffffffffu, bi0, 1);
    np_merge(bd0, bi0, od, oi);
    int bi = bi0;

    // --- rotation matrix from towards = -n, angle = 0 (R1 = I, rot = R2) ---
    float ax_x = -nx, ax_y = -ny, ax_z = -nz;
    float ay_x = -ax_y;   // = ny
    float ay_y =  ax_x;   // = -nx
    float ay_z = 0.0f;
    if (ay_x * ay_x + ay_y * ay_y + ay_z * ay_z == 0.0f) {
        ay_x = 0.0f; ay_y = 1.0f; ay_z = 0.0f;
    }
    float inva = 1.0f / sqrtf(ax_x * ax_x + ax_y * ax_y + ax_z * ax_z);
    ax_x *= inva; ax_y *= inva; ax_z *= inva;
    float invy = 1.0f / sqrtf(ay_x * ay_x + ay_y * ay_y + ay_z * ay_z);
    ay_x *= invy; ay_y *= invy; ay_z *= invy;
    float az_x = ax_y * ay_z - ax_z * ay_y;
    float az_y = ax_z * ay_x - ax_x * ay_z;
    float az_z = ax_x * ay_y - ax_y * ay_x;

    // --- outputs (stores split between the two lanes of the pair) ---
    float* out_xyz;
    float* out_rot;
    if (MODE == 0) {
        out_xyz = out + P;
        out_rot = out + P + 3 * (long long)P;
    } else {
        out_xyz = out + 2 * (long long)P;
        out_rot = out + 2 * (long long)P + 3 * (long long)P;
    }

    long long base3 = (long long)p * 3;
    long long base9 = (long long)p * 9;

    if (h == 0) {
        if (MODE == 0) {
            out[p] = (float)bi;
        } else {
            ((long long*)out)[p] = (long long)bi;
        }
        out_xyz[base3 + 0] = nx;
        out_xyz[base3 + 1] = ny;
        out_xyz[base3 + 2] = nz;
        // row-major [r][c]: col0 = ax, col1 = ay, col2 = az
        out_rot[base9 + 0] = ax_x;
        out_rot[base9 + 1] = ay_x;
        out_rot[base9 + 2] = az_x;
        out_rot[base9 + 3] = ax_y;
    } else {
        out_rot[base9 + 4] = ay_y;
        out_rot[base9 + 5] = az_y;
        out_rot[base9 + 6] = ax_z;
        out_rot[base9 + 7] = ay_z;
        out_rot[base9 + 8] = az_z;
    }
}

extern "C" void kernel_launch(void* const* d_in, const int* in_sizes, int n_in,
                              void* d_out, int out_size) {
    const float* normals = (const float*)d_in[0];
    const int*   idxs    = (const int*)d_in[1];
    float*       out     = (float*)d_out;

    const int B = 8;
    int P = in_sizes[1];            // B*S = 32768
    int S = P / B;                  // 4096
    int N = in_sizes[0] / (B * 3);  // 500000

    np_init_views_kernel<<<1, NUM_VIEW>>>();

    int threads = 256;
    long long total = 2LL * P;
    int blocks = (int)((total + threads - 1) / threads);
    if (out_size == 14 * P) {
        np_main_kernel<1><<<blocks, threads>>>(normals, idxs, out, N, S, P);
    } else {
        np_main_kernel<0><<<blocks, threads>>>(normals, idxs, out, N, S, P);
    }
}

// round 3
// speedup vs baseline: 1.2792x; 1.1429x over previous
#include <cuda_runtime.h>
#include <math_constants.h>

#define NUM_VIEW 300

// Precomputed view codebook: (x, y, z, |v|^2) per view.
__device__ float4 g_views[NUM_VIEW];

// Spread across many blocks: FP64 sincos is slow, don't serialize on one SM.
__global__ void np_init_views_kernel() {
    int i = blockIdx.x * blockDim.x + threadIdx.x;
    if (i < NUM_VIEW) {
        // Match numpy float64 construction exactly, then cast to float32.
        double di  = (double)i;
        double zi  = (2.0 * di + 1.0) / (double)NUM_VIEW - 1.0;
        double r2  = 1.0 - zi * zi;
        if (r2 < 0.0) r2 = 0.0;
        double r   = sqrt(r2);
        const double PHI = (sqrt(5.0) - 1.0) * 0.5;
        double ang = 2.0 * di * CUDART_PI * PHI;
        double s, c;
        sincos(ang, &s, &c);
        float xf = (float)(r * c);
        float yf = (float)(r * s);
        float zf = (float)zi;
        // fp32 sum-of-squares, no FMA contraction (match jnp.sum(views*views))
        float vv = __fadd_rn(__fadd_rn(__fmul_rn(xf, xf), __fmul_rn(yf, yf)),
                             __fmul_rn(zf, zf));
        g_views[i] = make_float4(xf, yf, zf, vv);
    }
}

__device__ __forceinline__ void np_merge(float& d0, int& i0, float d1, int i1) {
    // first-min (lowest index) wins on ties — exact jnp.argmin semantics
    if (d1 < d0 || (d1 == d0 && i1 < i0)) { d0 = d1; i0 = i1; }
}

// 4 threads per point. Lane h in {0..3} scans views [h*75, h*75+75).
// MODE 0: indices written as float32 (output = 13*P floats)
// MODE 1: indices written as int64 bit-pattern (output = 14*P float slots)
template <int MODE>
__global__ void np_main_kernel(const float* __restrict__ normals,
                               const int*   __restrict__ idxs,
                               float*       __restrict__ out,
                               int N, int S, int P) {
    __shared__ float4 sv[NUM_VIEW];
    for (int i = threadIdx.x; i < NUM_VIEW; i += blockDim.x)
        sv[i] = g_views[i];
    __syncthreads();

    int t = blockIdx.x * blockDim.x + threadIdx.x;
    int p = t >> 2;
    int h = t & 3;
    if (p >= P) return;

    int b   = p / S;
    int idx = idxs[p];
    const float* nptr = normals + ((long long)b * N + idx) * 3;
    float nx = __ldg(nptr + 0);
    float ny = __ldg(nptr + 1);
    float nz = __ldg(nptr + 2);

    float nn = nx * nx + ny * ny + nz * nz;

    // --- argmin over this lane's 75 views: 5 accumulators x 15 iterations ---
    int v = h * 75;
    float bd0 = CUDART_INF_F, bd1 = CUDART_INF_F, bd2 = CUDART_INF_F,
          bd3 = CUDART_INF_F, bd4 = CUDART_INF_F;
    int   bi0 = 0, bi1 = 0, bi2 = 0, bi3 = 0, bi4 = 0;

#pragma unroll 1
    for (int k = 0; k < 15; k++) {
        float4 V0 = sv[v + 0];
        float4 V1 = sv[v + 1];
        float4 V2 = sv[v + 2];
        float4 V3 = sv[v + 3];
        float4 V4 = sv[v + 4];
        float dot0 = nx * V0.x + ny * V0.y + nz * V0.z;
        float dot1 = nx * V1.x + ny * V1.y + nz * V1.z;
        float dot2 = nx * V2.x + ny * V2.y + nz * V2.z;
        float dot3 = nx * V3.x + ny * V3.y + nz * V3.z;
        float dot4 = nx * V4.x + ny * V4.y + nz * V4.z;
        float d0 = nn - 2.0f * dot0 + V0.w;
        float d1 = nn - 2.0f * dot1 + V1.w;
        float d2 = nn - 2.0f * dot2 + V2.w;
        float d3 = nn - 2.0f * dot3 + V3.w;
        float d4 = nn - 2.0f * dot4 + V4.w;
        if (d0 < bd0) { bd0 = d0; bi0 = v + 0; }
        if (d1 < bd1) { bd1 = d1; bi1 = v + 1; }
        if (d2 < bd2) { bd2 = d2; bi2 = v + 2; }
        if (d3 < bd3) { bd3 = d3; bi3 = v + 3; }
        if (d4 < bd4) { bd4 = d4; bi4 = v + 4; }
        v += 5;
    }

    // merge 5 accumulators (index tie-break keeps exact first-min semantics)
    np_merge(bd0, bi0, bd1, bi1);
    np_merge(bd2, bi2, bd3, bi3);
    np_merge(bd0, bi0, bd2, bi2);
    np_merge(bd0, bi0, bd4, bi4);

    // butterfly merge across the 4 lanes of the point
    float od; int oi;
    od = __shfl_xor_sync(0xffffffffu, bd0, 1);
    oi = __shfl_xor_sync(0xffffffffu, bi0, 1);
    np_merge(bd0, bi0, od, oi);
    od = __shfl_xor_sync(0xffffffffu, bd0, 2);
    oi = __shfl_xor_sync(0xffffffffu, bi0, 2);
    np_merge(bd0, bi0, od, oi);
    int bi = bi0;

    // --- rotation matrix from towards = -n, angle = 0 (R1 = I, rot = R2) ---
    float ax_x = -nx, ax_y = -ny, ax_z = -nz;
    float ay_x = -ax_y;   // = ny
    float ay_y =  ax_x;   // = -nx
    float ay_z = 0.0f;
    if (ay_x * ay_x + ay_y * ay_y + ay_z * ay_z == 0.0f) {
        ay_x = 0.0f; ay_y = 1.0f; ay_z = 0.0f;
    }
    float inva = 1.0f / sqrtf(ax_x * ax_x + ax_y * ax_y + ax_z * ax_z);
    ax_x *= inva; ax_y *= inva; ax_z *= inva;
    float invy = 1.0f / sqrtf(ay_x * ay_x + ay_y * ay_y + ay_z * ay_z);
    ay_x *= invy; ay_y *= invy; ay_z *= invy;
    float az_x = ax_y * ay_z - ax_z * ay_y;
    float az_y = ax_z * ay_x - ax_x * ay_z;
    float az_z = ax_x * ay_y - ax_y * ay_x;

    // --- outputs (stores split between the four lanes of the point) ---
    float* out_xyz;
    float* out_rot;
    if (MODE == 0) {
        out_xyz = out + P;
        out_rot = out + P + 3 * (long long)P;
    } else {
        out_xyz = out + 2 * (long long)P;
        out_rot = out + 2 * (long long)P + 3 * (long long)P;
    }

    long long base3 = (long long)p * 3;
    long long base9 = (long long)p * 9;

    // row-major [r][c]: col0 = ax, col1 = ay, col2 = az
    // rot = {ax_x, ay_x, az_x, ax_y, ay_y, az_y, ax_z, ay_z, az_z}
    if (h == 0) {
        if (MODE == 0) {
            out[p] = (float)bi;
        } else {
            ((long long*)out)[p] = (long long)bi;
        }
        out_xyz[base3 + 0] = nx;
        out_xyz[base3 + 1] = ny;
    } else if (h == 1) {
        out_xyz[base3 + 2] = nz;
        out_rot[base9 + 0] = ax_x;
        out_rot[base9 + 1] = ay_x;
        out_rot[base9 + 2] = az_x;
    } else if (h == 2) {
        out_rot[base9 + 3] = ax_y;
        out_rot[base9 + 4] = ay_y;
        out_rot[base9 + 5] = az_y;
    } else {
        out_rot[base9 + 6] = ax_z;
        out_rot[base9 + 7] = ay_z;
        out_rot[base9 + 8] = az_z;
    }
}

extern "C" void kernel_launch(void* const* d_in, const int* in_sizes, int n_in,
                              void* d_out, int out_size) {
    const float* normals = (const float*)d_in[0];
    const int*   idxs    = (const int*)d_in[1];
    float*       out     = (float*)d_out;

    const int B = 8;
    int P = in_sizes[1];            // B*S = 32768
    int S = P / B;                  // 4096
    int N = in_sizes[0] / (B * 3);  // 500000

    // 75 blocks x 4 threads: spread the slow FP64 sincos across ~75 SMs
    np_init_views_kernel<<<75, 4>>>();

    int threads = 256;
    long long total = 4LL * P;
    int blocks = (int)((total + threads - 1) / threads);
    if (out_size == 14 * P) {
        np_main_kernel<1><<<blocks, threads>>>(normals, idxs, out, N, S, P);
    } else {
        np_main_kernel<0><<<blocks, threads>>>(normals, idxs, out, N, S, P);
    }
}

// round 4
// speedup vs baseline: 1.4812x; 1.1579x over previous
#include <cuda_runtime.h>
#include <math_constants.h>

#define NUM_VIEW 300

// Precomputed view codebook: (x, y, z, -|v|^2/2) per view.
__device__ float4 g_views[NUM_VIEW];

// Spread across many blocks: FP64 sincos is slow, don't serialize on one SM.
__global__ void np_init_views_kernel() {
    int i = blockIdx.x * blockDim.x + threadIdx.x;
    if (i < NUM_VIEW) {
        // Match numpy float64 construction exactly, then cast to float32.
        double di  = (double)i;
        double zi  = (2.0 * di + 1.0) / (double)NUM_VIEW - 1.0;
        double r2  = 1.0 - zi * zi;
        if (r2 < 0.0) r2 = 0.0;
        double r   = sqrt(r2);
        const double PHI = (sqrt(5.0) - 1.0) * 0.5;
        double ang = 2.0 * di * CUDART_PI * PHI;
        double s, c;
        sincos(ang, &s, &c);
        float xf = (float)(r * c);
        float yf = (float)(r * s);
        float zf = (float)zi;
        float vv = __fadd_rn(__fadd_rn(__fmul_rn(xf, xf), __fmul_rn(yf, yf)),
                             __fmul_rn(zf, zf));
        g_views[i] = make_float4(xf, yf, zf, -0.5f * vv);
    }
}

__device__ __forceinline__ void np_merge_max(float& s0, int& i0, float s1, int i1) {
    // first-max (lowest index) wins on ties — matches argmin-first semantics
    if (s1 > s0 || (s1 == s0 && i1 < i0)) { s0 = s1; i0 = i1; }
}

// 2 threads per point. Lane h in {0,1} scans views [h*150, h*150+150).
// argmin(|n-v|^2) == argmax(dot(n,v) - |v|^2/2): 3 FFMA per view.
// MODE 0: indices written as float32 (output = 13*P floats)
// MODE 1: indices written as int64 bit-pattern (output = 14*P float slots)
template <int MODE>
__global__ void np_main_kernel(const float* __restrict__ normals,
                               const int*   __restrict__ idxs,
                               float*       __restrict__ out,
                               int N, int S, int P) {
    __shared__ float4 sv[NUM_VIEW];
    for (int i = threadIdx.x; i < NUM_VIEW; i += blockDim.x)
        sv[i] = g_views[i];
    __syncthreads();

    int t = blockIdx.x * blockDim.x + threadIdx.x;
    int p = t >> 1;
    int h = t & 1;
    if (p >= P) return;

    int b   = p / S;
    int idx = idxs[p];
    const float* nptr = normals + ((long long)b * N + idx) * 3;
    float nx = __ldg(nptr + 0);
    float ny = __ldg(nptr + 1);
    float nz = __ldg(nptr + 2);

    // --- argmax over this lane's 150 views: 6 accumulators x 25 iterations ---
    int v = h * 150;
    float bs0 = -CUDART_INF_F, bs1 = -CUDART_INF_F, bs2 = -CUDART_INF_F,
          bs3 = -CUDART_INF_F, bs4 = -CUDART_INF_F, bs5 = -CUDART_INF_F;
    int   bi0 = 0, bi1 = 0, bi2 = 0, bi3 = 0, bi4 = 0, bi5 = 0;

#pragma unroll 1
    for (int k = 0; k < 25; k++) {
        float4 V0 = sv[v + 0];
        float4 V1 = sv[v + 1];
        float4 V2 = sv[v + 2];
        float4 V3 = sv[v + 3];
        float4 V4 = sv[v + 4];
        float4 V5 = sv[v + 5];
        float s0 = fmaf(nx, V0.x, fmaf(ny, V0.y, fmaf(nz, V0.z, V0.w)));
        float s1 = fmaf(nx, V1.x, fmaf(ny, V1.y, fmaf(nz, V1.z, V1.w)));
        float s2 = fmaf(nx, V2.x, fmaf(ny, V2.y, fmaf(nz, V2.z, V2.w)));
        float s3 = fmaf(nx, V3.x, fmaf(ny, V3.y, fmaf(nz, V3.z, V3.w)));
        float s4 = fmaf(nx, V4.x, fmaf(ny, V4.y, fmaf(nz, V4.z, V4.w)));
        float s5 = fmaf(nx, V5.x, fmaf(ny, V5.y, fmaf(nz, V5.z, V5.w)));
        if (s0 > bs0) { bs0 = s0; bi0 = v + 0; }
        if (s1 > bs1) { bs1 = s1; bi1 = v + 1; }
        if (s2 > bs2) { bs2 = s2; bi2 = v + 2; }
        if (s3 > bs3) { bs3 = s3; bi3 = v + 3; }
        if (s4 > bs4) { bs4 = s4; bi4 = v + 4; }
        if (s5 > bs5) { bs5 = s5; bi5 = v + 5; }
        v += 6;
    }

    // merge 6 accumulators (index tie-break keeps exact first-win semantics)
    np_merge_max(bs0, bi0, bs1, bi1);
    np_merge_max(bs2, bi2, bs3, bi3);
    np_merge_max(bs4, bi4, bs5, bi5);
    np_merge_max(bs0, bi0, bs2, bi2);
    np_merge_max(bs0, bi0, bs4, bi4);

    // merge across the lane pair
    float os = __shfl_xor_sync(0xffffffffu, bs0, 1);
    int   oi = __shfl_xor_sync(0xffffffffu, bi0, 1);
    np_merge_max(bs0, bi0, os, oi);
    int bi = bi0;

    // --- rotation matrix from towards = -n, angle = 0 (R1 = I, rot = R2) ---
    float ax_x = -nx, ax_y = -ny, ax_z = -nz;
    float ay_x = -ax_y;   // = ny
    float ay_y =  ax_x;   // = -nx
    float ay_z = 0.0f;
    if (ay_x * ay_x + ay_y * ay_y + ay_z * ay_z == 0.0f) {
        ay_x = 0.0f; ay_y = 1.0f; ay_z = 0.0f;
    }
    float inva = 1.0f / sqrtf(ax_x * ax_x + ax_y * ax_y + ax_z * ax_z);
    ax_x *= inva; ax_y *= inva; ax_z *= inva;
    float invy = 1.0f / sqrtf(ay_x * ay_x + ay_y * ay_y + ay_z * ay_z);
    ay_x *= invy; ay_y *= invy; ay_z *= invy;
    float az_x = ax_y * ay_z - ax_z * ay_y;
    float az_y = ax_z * ay_x - ax_x * ay_z;
    float az_z = ax_x * ay_y - ax_y * ay_x;

    // --- outputs (stores split between the two lanes of the pair) ---
    float* out_xyz;
    float* out_rot;
    if (MODE == 0) {
        out_xyz = out + P;
        out_rot = out + P + 3 * (long long)P;
    } else {
        out_xyz = out + 2 * (long long)P;
        out_rot = out + 2 * (long long)P + 3 * (long long)P;
    }

    long long base3 = (long long)p * 3;
    long long base9 = (long long)p * 9;

    if (h == 0) {
        if (MODE == 0) {
            out[p] = (float)bi;
        } else {
            ((long long*)out)[p] = (long long)bi;
        }
        out_xyz[base3 + 0] = nx;
        out_xyz[base3 + 1] = ny;
        out_xyz[base3 + 2] = nz;
        // row-major [r][c]: col0 = ax, col1 = ay, col2 = az
        out_rot[base9 + 0] = ax_x;
        out_rot[base9 + 1] = ay_x;
        out_rot[base9 + 2] = az_x;
        out_rot[base9 + 3] = ax_y;
    } else {
        out_rot[base9 + 4] = ay_y;
        out_rot[base9 + 5] = az_y;
        out_rot[base9 + 6] = ax_z;
        out_rot[base9 + 7] = ay_z;
        out_rot[base9 + 8] = az_z;
    }
}

extern "C" void kernel_launch(void* const* d_in, const int* in_sizes, int n_in,
                              void* d_out, int out_size) {
    const float* normals = (const float*)d_in[0];
    const int*   idxs    = (const int*)d_in[1];
    float*       out     = (float*)d_out;

    const int B = 8;
    int P = in_sizes[1];            // B*S = 32768
    int S = P / B;                  // 4096
    int N = in_sizes[0] / (B * 3);  // 500000

    np_init_views_kernel<<<75, 4>>>();

    int threads = 256;
    long long total = 2LL * P;
    int blocks = (int)((total + threads - 1) / threads);
    if (out_size == 14 * P) {
        np_main_kernel<1><<<blocks, threads>>>(normals, idxs, out, N, S, P);
    } else {
        np_main_kernel<0><<<blocks, threads>>>(normals, idxs, out, N, S, P);
    }
}